// round 13
// baseline (speedup 1.0000x reference)
#include <cuda_runtime.h>
#include <math.h>
#include <cstdint>

#define HH 1024
#define WW 1024
#define CC 128
#define NW 16                 // warps per block = columns per block (incl. 2 halo)
#define TPB (NW * 32)
#define COUT (NW - 2)         // 14 output columns per block
#define ROWG 256              // rows per block (74 x 4 = 296 blocks = exactly 1 wave)
#define BATCH 32              // rows per deferred dot-reduce burst

#define VS_FLOATS (2 * 2 * NW * CC)        // 8192  (parity, rowpair, warp, ch)
#define DP_FLOATS (NW * BATCH * 33)        // 16896 (warp, rowslot, lane+pad)
#define SMEM_FLOATS (VS_FLOATS + DP_FLOATS)

// ---- packed f32x2 primitives (sm_103a; PTX-only, ptxas won't auto-fuse) ----
__device__ __forceinline__ uint64_t f2mul(uint64_t a, uint64_t b) {
    uint64_t r; asm("mul.rn.f32x2 %0,%1,%2;" : "=l"(r) : "l"(a), "l"(b)); return r;
}
__device__ __forceinline__ uint64_t f2add(uint64_t a, uint64_t b) {
    uint64_t r; asm("add.rn.f32x2 %0,%1,%2;" : "=l"(r) : "l"(a), "l"(b)); return r;
}
__device__ __forceinline__ uint64_t f2fma(uint64_t a, uint64_t b, uint64_t c) {
    uint64_t r; asm("fma.rn.f32x2 %0,%1,%2,%3;" : "=l"(r) : "l"(a), "l"(b), "l"(c)); return r;
}
__device__ __forceinline__ uint64_t pack2(float x, float y) {
    uint64_t r; asm("mov.b64 %0,{%1,%2};" : "=l"(r) : "f"(x), "f"(y)); return r;
}
__device__ __forceinline__ float hsum2(uint64_t v) {
    float x, y; asm("mov.b64 {%0,%1},%2;" : "=f"(x), "=f"(y) : "l"(v)); return x + y;
}
__device__ __forceinline__ float dot4p(ulonglong2 v) {
    return hsum2(f2fma(v.y, v.y, f2mul(v.x, v.x)));
}

// FMA-pipe rsqrt: bit-hack seed + 2 Newton iterations (~5e-6 rel err).
// Avoids the MUFU queue burst when all 16 warps hit rsqrt post-barrier.
__device__ __forceinline__ float nrsqrt(float x) {
    float y = __uint_as_float(0x5f3759dfu - (__float_as_uint(x) >> 1));
    const float h = 0.5f * x;
    y = y * fmaf(-h * y, y, 1.5f);
    y = y * fmaf(-h * y, y, 1.5f);
    return y;
}

// reduce TWO independent values across the warp in one shared butterfly (6 SHFL)
__device__ __forceinline__ float2 redux2(float a, float b, int lane) {
    const unsigned full = 0xffffffffu;
    float z = (lane < 16) ? a : b;
    float w = (lane < 16) ? b : a;
    w = __shfl_xor_sync(full, w, 16);
    z += w;
    #pragma unroll
    for (int o = 8; o > 0; o >>= 1)
        z += __shfl_xor_sync(full, z, o);
    float t = __shfl_xor_sync(full, z, 16);
    float sa = (lane < 16) ? z : t;
    float sb = (lane < 16) ? t : z;
    return make_float2(sa, sb);
}

__global__ void __launch_bounds__(TPB, 2)
cos_sim_stream(const float* __restrict__ in, float* __restrict__ out)
{
    extern __shared__ float smem[];
    float* vsb = smem;                 // vertical-sum exchange ring
    float* dp  = smem + VS_FLOATS;     // per-warp deferred dot partials

    const int lane = threadIdx.x & 31;
    const int wid  = threadIdx.x >> 5;
    const int col  = blockIdx.x * COUT + wid - 1;     // wid 0 / NW-1 = halo
    const bool colok = ((unsigned)col < (unsigned)WW);
    const bool inner = (wid >= 1) && (wid <= COUT);
    const bool outok = colok && inner;
    const int r0 = blockIdx.y * ROWG;

    float* dprow = dp + wid * (BATCH * 33);

    const float* gcol = in + (size_t)col * CC + lane * 4;
    const size_t rowstep = (size_t)WW * CC;
    auto ld = [&](int h) -> ulonglong2 {
        ulonglong2 v; v.x = 0ull; v.y = 0ull;
        if (colok && (unsigned)h < (unsigned)HH)
            v = *reinterpret_cast<const ulonglong2*>(gcol + (size_t)h * rowstep);
        return v;
    };
    auto scalev = [&](ulonglong2 v, float inv) -> ulonglong2 {
        const uint64_t ip = pack2(inv, inv);
        ulonglong2 r; r.x = f2mul(v.x, ip); r.y = f2mul(v.y, ip); return r;
    };

    // ---- preamble: normalize rows r0-1, r0 (paired reduce); 4 rows staged ----
    ulonglong2 xnA, xnB;
    {
        ulonglong2 ra = ld(r0 - 1), rb = ld(r0);
        float2 ss = redux2(dot4p(ra), dot4p(rb), lane);
        xnA = scalev(ra, (ss.x >= 1e-16f) ? nrsqrt(ss.x) : 1e8f);
        xnB = scalev(rb, (ss.y >= 1e-16f) ? nrsqrt(ss.y) : 1e8f);
    }
    ulonglong2 stg[2][2];
    stg[0][0] = ld(r0 + 1);  stg[0][1] = ld(r0 + 2);
    stg[1][0] = ld(r0 + 3);  stg[1][1] = ld(r0 + 4);

    #pragma unroll 2
    for (int k = 0; k < ROWG / 2; k++) {
        const int i = 2 * k;
        const int h = r0 + i;
        const int p = k & 1;

        // normalize rows h+1, h+2 with ONE paired butterfly
        ulonglong2 s0 = stg[p][0], s1 = stg[p][1];
        float2 ss = redux2(dot4p(s0), dot4p(s1), lane);
        const ulonglong2 xnC = scalev(s0, (ss.x >= 1e-16f) ? nrsqrt(ss.x) : 1e8f);
        const ulonglong2 xnD = scalev(s1, (ss.y >= 1e-16f) ? nrsqrt(ss.y) : 1e8f);
        stg[p][0] = ld(h + 5);                 // refill, 4 rows ahead
        stg[p][1] = ld(h + 6);

        ulonglong2 v0, v1;                     // vertical 3-sums (packed)
        v0.x = f2add(f2add(xnA.x, xnB.x), xnC.x);
        v0.y = f2add(f2add(xnA.y, xnB.y), xnC.y);
        v1.x = f2add(f2add(xnB.x, xnC.x), xnD.x);
        v1.y = f2add(f2add(xnB.y, xnC.y), xnD.y);

        float* base0 = vsb + ((p * 2 + 0) * NW + wid) * CC + lane * 4;
        float* base1 = base0 + NW * CC;
        *reinterpret_cast<ulonglong2*>(base0) = v0;
        *reinterpret_cast<ulonglong2*>(base1) = v1;
        __syncthreads();                       // one barrier per 2 rows

        if (inner) {                           // warp-uniform
            const ulonglong2 l0 = *reinterpret_cast<const ulonglong2*>(base0 - CC);
            const ulonglong2 q0 = *reinterpret_cast<const ulonglong2*>(base0 + CC);
            const ulonglong2 l1 = *reinterpret_cast<const ulonglong2*>(base1 - CC);
            const ulonglong2 q1 = *reinterpret_cast<const ulonglong2*>(base1 + CC);

            uint64_t t0 = f2mul(xnB.x, f2add(f2add(l0.x, v0.x), q0.x));
            t0 = f2fma(xnB.y, f2add(f2add(l0.y, v0.y), q0.y), t0);
            uint64_t t1 = f2mul(xnC.x, f2add(f2add(l1.x, v1.x), q1.x));
            t1 = f2fma(xnC.y, f2add(f2add(l1.y, v1.y), q1.y), t1);

            dprow[(i & 31) * 33 + lane]       = hsum2(t0);   // defer lane-reduce
            dprow[((i + 1) & 31) * 33 + lane] = hsum2(t1);

            if ((i & 31) == 30) {              // batch of 32 rows complete
                __syncwarp();
                if (outok) {
                    float s = 0.f;
                    #pragma unroll
                    for (int j = 0; j < 32; j++) s += dprow[lane * 33 + j];
                    out[(size_t)(h - 30 + lane) * WW + col] = s - 1.0f;
                }
                __syncwarp();
            }
        }
        xnA = xnC;  xnB = xnD;
    }
}

extern "C" void kernel_launch(void* const* d_in, const int* in_sizes, int n_in,
                              void* d_out, int out_size)
{
    const float* in = (const float*)d_in[0];
    float* out = (float*)d_out;

    const size_t smem_bytes = SMEM_FLOATS * sizeof(float);   // ~98 KB
    cudaFuncSetAttribute(cos_sim_stream,
                         cudaFuncAttributeMaxDynamicSharedMemorySize,
                         (int)smem_bytes);

    dim3 grid((WW + COUT - 1) / COUT, HH / ROWG);   // 74 x 4 = 296 = one full wave
    cos_sim_stream<<<grid, TPB, smem_bytes>>>(in, out);
}

// round 14
// speedup vs baseline: 1.0658x; 1.0658x over previous
#include <cuda_runtime.h>
#include <math.h>
#include <cstdint>

#define HH 1024
#define WW 1024
#define CC 128
#define NW 16                 // warps per block = columns per block (incl. 2 halo)
#define TPB (NW * 32)
#define COUT (NW - 2)         // 14 output columns per block
#define ROWG 128              // rows per block
#define BATCH 32              // rows per deferred dot-reduce burst

#define VS_FLOATS (2 * 2 * NW * CC)        // 8192  (parity, rowpair, warp, ch)
#define DP_FLOATS (NW * BATCH * 33)        // 16896 (warp, rowslot, lane+pad)
#define SMEM_FLOATS (VS_FLOATS + DP_FLOATS)

// ---- packed f32x2 primitives (sm_103a; PTX-only, ptxas won't auto-fuse) ----
__device__ __forceinline__ uint64_t f2mul(uint64_t a, uint64_t b) {
    uint64_t r; asm("mul.rn.f32x2 %0,%1,%2;" : "=l"(r) : "l"(a), "l"(b)); return r;
}
__device__ __forceinline__ uint64_t f2add(uint64_t a, uint64_t b) {
    uint64_t r; asm("add.rn.f32x2 %0,%1,%2;" : "=l"(r) : "l"(a), "l"(b)); return r;
}
__device__ __forceinline__ uint64_t f2fma(uint64_t a, uint64_t b, uint64_t c) {
    uint64_t r; asm("fma.rn.f32x2 %0,%1,%2,%3;" : "=l"(r) : "l"(a), "l"(b), "l"(c)); return r;
}
__device__ __forceinline__ uint64_t pack2(float x, float y) {
    uint64_t r; asm("mov.b64 %0,{%1,%2};" : "=l"(r) : "f"(x), "f"(y)); return r;
}
__device__ __forceinline__ float hsum2(uint64_t v) {
    float x, y; asm("mov.b64 {%0,%1},%2;" : "=f"(x), "=f"(y) : "l"(v)); return x + y;
}
__device__ __forceinline__ float dot4p(ulonglong2 v) {
    return hsum2(f2fma(v.y, v.y, f2mul(v.x, v.x)));
}

// reduce TWO independent values across the warp in one shared butterfly (6 SHFL)
__device__ __forceinline__ float2 redux2(float a, float b, int lane) {
    const unsigned full = 0xffffffffu;
    float z = (lane < 16) ? a : b;
    float w = (lane < 16) ? b : a;
    w = __shfl_xor_sync(full, w, 16);
    z += w;
    #pragma unroll
    for (int o = 8; o > 0; o >>= 1)
        z += __shfl_xor_sync(full, z, o);
    float t = __shfl_xor_sync(full, z, 16);
    float sa = (lane < 16) ? z : t;
    float sb = (lane < 16) ? t : z;
    return make_float2(sa, sb);
}

__global__ void __launch_bounds__(TPB, 2)
cos_sim_stream(const float* __restrict__ in, float* __restrict__ out)
{
    extern __shared__ float smem[];
    float* vsb = smem;                 // vertical-sum exchange ring (2 slots)
    float* dp  = smem + VS_FLOATS;     // per-warp deferred dot partials

    const int lane = threadIdx.x & 31;
    const int wid  = threadIdx.x >> 5;
    const int col  = blockIdx.x * COUT + wid - 1;     // wid 0 / NW-1 = halo
    const bool colok = ((unsigned)col < (unsigned)WW);
    const bool inner = (wid >= 1) && (wid <= COUT);
    const bool outok = colok && inner;
    const int r0 = blockIdx.y * ROWG;

    float* dprow = dp + wid * (BATCH * 33);

    const float* gcol = in + (size_t)col * CC + lane * 4;
    const size_t rowstep = (size_t)WW * CC;
    auto ld = [&](int h) -> ulonglong2 {
        ulonglong2 v; v.x = 0ull; v.y = 0ull;
        if (colok && (unsigned)h < (unsigned)HH)
            v = *reinterpret_cast<const ulonglong2*>(gcol + (size_t)h * rowstep);
        return v;
    };
    auto scalev = [&](ulonglong2 v, float inv) -> ulonglong2 {
        const uint64_t ip = pack2(inv, inv);
        ulonglong2 r; r.x = f2mul(v.x, ip); r.y = f2mul(v.y, ip); return r;
    };

    // ---- preamble: normalize rows r0-1, r0; stage raw rows r0+1, r0+2 ----
    ulonglong2 xnA, xnB, xnP;
    {
        ulonglong2 ra = ld(r0 - 1), rb = ld(r0);
        float2 ss = redux2(dot4p(ra), dot4p(rb), lane);
        xnA = scalev(ra, (ss.x >= 1e-16f) ? rsqrtf(ss.x) : 1e8f);
        xnB = scalev(rb, (ss.y >= 1e-16f) ? rsqrtf(ss.y) : 1e8f);
        xnP = xnA;                     // unused at k=0
    }
    ulonglong2 stg0 = ld(r0 + 1), stg1 = ld(r0 + 2);

    // iter k: PRODUCE vsums for rows (2k, 2k+1) into slot k&1;
    //         CONSUME rows (2k-2, 2k-1) from slot (k-1)&1 (written last iter,
    //         so the LDS+dot chain overlaps the redux/normalize chain).
    for (int k = 0; k <= ROWG / 2; k++) {
        const int p = k & 1;

        // --- consume phase: output rows 2k-2, 2k-1 (centers xnP, xnA) ---
        if (k > 0 && inner) {
            const int i = 2 * k - 2;
            const float* ob0 = vsb + (((1 - p) * 2 + 0) * NW + wid) * CC + lane * 4;
            const float* ob1 = ob0 + NW * CC;
            const ulonglong2 l0 = *reinterpret_cast<const ulonglong2*>(ob0 - CC);
            const ulonglong2 o0 = *reinterpret_cast<const ulonglong2*>(ob0);
            const ulonglong2 q0 = *reinterpret_cast<const ulonglong2*>(ob0 + CC);
            const ulonglong2 l1 = *reinterpret_cast<const ulonglong2*>(ob1 - CC);
            const ulonglong2 o1 = *reinterpret_cast<const ulonglong2*>(ob1);
            const ulonglong2 q1 = *reinterpret_cast<const ulonglong2*>(ob1 + CC);

            uint64_t t0 = f2mul(xnP.x, f2add(f2add(l0.x, o0.x), q0.x));
            t0 = f2fma(xnP.y, f2add(f2add(l0.y, o0.y), q0.y), t0);
            uint64_t t1 = f2mul(xnA.x, f2add(f2add(l1.x, o1.x), q1.x));
            t1 = f2fma(xnA.y, f2add(f2add(l1.y, o1.y), q1.y), t1);

            dprow[(i & 31) * 33 + lane]       = hsum2(t0);
            dprow[((i + 1) & 31) * 33 + lane] = hsum2(t1);

            if ((i & 31) == 30) {              // batch of 32 rows complete
                __syncwarp();
                if (outok) {
                    float s = 0.f;
                    #pragma unroll
                    for (int j = 0; j < 32; j++) s += dprow[lane * 33 + j];
                    out[(size_t)(r0 + i - 30 + lane) * WW + col] = s - 1.0f;
                }
                __syncwarp();
            }
        }

        // --- produce phase: rows 2k, 2k+1 ---
        if (k < ROWG / 2) {
            const int h = r0 + 2 * k;

            // normalize rows h+1, h+2 (staged last iteration)
            float2 ss = redux2(dot4p(stg0), dot4p(stg1), lane);
            const ulonglong2 xnC = scalev(stg0, (ss.x >= 1e-16f) ? rsqrtf(ss.x) : 1e8f);
            const ulonglong2 xnD = scalev(stg1, (ss.y >= 1e-16f) ? rsqrtf(ss.y) : 1e8f);
            stg0 = ld(h + 3);                  // consumed next iteration
            stg1 = ld(h + 4);

            ulonglong2 v0, v1;                 // vertical 3-sums (packed)
            v0.x = f2add(f2add(xnA.x, xnB.x), xnC.x);
            v0.y = f2add(f2add(xnA.y, xnB.y), xnC.y);
            v1.x = f2add(f2add(xnB.x, xnC.x), xnD.x);
            v1.y = f2add(f2add(xnB.y, xnC.y), xnD.y);

            float* base0 = vsb + ((p * 2 + 0) * NW + wid) * CC + lane * 4;
            float* base1 = base0 + NW * CC;
            *reinterpret_cast<ulonglong2*>(base0) = v0;
            *reinterpret_cast<ulonglong2*>(base1) = v1;

            xnP = xnB;  xnA = xnC;  xnB = xnD;
            __syncthreads();                   // publishes slot p for iter k+1
        }
    }
}

extern "C" void kernel_launch(void* const* d_in, const int* in_sizes, int n_in,
                              void* d_out, int out_size)
{
    const float* in = (const float*)d_in[0];
    float* out = (float*)d_out;

    const size_t smem_bytes = SMEM_FLOATS * sizeof(float);   // ~98 KB
    cudaFuncSetAttribute(cos_sim_stream,
                         cudaFuncAttributeMaxDynamicSharedMemorySize,
                         (int)smem_bytes);

    dim3 grid((WW + COUT - 1) / COUT, HH / ROWG);   // 74 x 8
    cos_sim_stream<<<grid, TPB, smem_bytes>>>(in, out);
}

// round 15
// speedup vs baseline: 1.1097x; 1.0411x over previous
#include <cuda_runtime.h>
#include <math.h>
#include <cstdint>

#define HH 1024
#define WW 1024
#define CC 128
#define NW 16                 // warps per block = columns per block (incl. 2 halo)
#define TPB (NW * 32)
#define COUT (NW - 2)         // 14 output columns per block
#define ROWG 128              // rows per block
#define BATCH 32              // rows per deferred dot-reduce burst

#define SLOTB 16384           // bytes per parity slot (2 * NW * CC * 4)
#define RPB   8192            // bytes per rowpair     (NW * CC * 4)

#define VS_FLOATS (2 * 2 * NW * CC)        // 8192
#define DP_FLOATS (NW * BATCH * 33)        // 16896
#define SMEM_FLOATS (VS_FLOATS + DP_FLOATS)

// ---- packed f32x2 primitives (sm_103a; PTX-only) ----
__device__ __forceinline__ uint64_t f2mul(uint64_t a, uint64_t b) {
    uint64_t r; asm("mul.rn.f32x2 %0,%1,%2;" : "=l"(r) : "l"(a), "l"(b)); return r;
}
__device__ __forceinline__ uint64_t f2add(uint64_t a, uint64_t b) {
    uint64_t r; asm("add.rn.f32x2 %0,%1,%2;" : "=l"(r) : "l"(a), "l"(b)); return r;
}
__device__ __forceinline__ uint64_t f2fma(uint64_t a, uint64_t b, uint64_t c) {
    uint64_t r; asm("fma.rn.f32x2 %0,%1,%2,%3;" : "=l"(r) : "l"(a), "l"(b), "l"(c)); return r;
}
__device__ __forceinline__ uint64_t pack2(float x, float y) {
    uint64_t r; asm("mov.b64 %0,{%1,%2};" : "=l"(r) : "f"(x), "f"(y)); return r;
}
__device__ __forceinline__ float hsum2(uint64_t v) {
    float x, y; asm("mov.b64 {%0,%1},%2;" : "=f"(x), "=f"(y) : "l"(v)); return x + y;
}
__device__ __forceinline__ float dot4p(ulonglong2 v) {
    return hsum2(f2fma(v.y, v.y, f2mul(v.x, v.x)));
}

// reduce TWO independent values across the warp in one shared butterfly (6 SHFL)
__device__ __forceinline__ float2 redux2(float a, float b, int lane) {
    const unsigned full = 0xffffffffu;
    float z = (lane < 16) ? a : b;
    float w = (lane < 16) ? b : a;
    w = __shfl_xor_sync(full, w, 16);
    z += w;
    #pragma unroll
    for (int o = 8; o > 0; o >>= 1)
        z += __shfl_xor_sync(full, z, o);
    float t = __shfl_xor_sync(full, z, 16);
    float sa = (lane < 16) ? z : t;
    float sb = (lane < 16) ? t : z;
    return make_float2(sa, sb);
}

__global__ void __launch_bounds__(TPB, 2)
cos_sim_stream(const float* __restrict__ in, float* __restrict__ out)
{
    extern __shared__ float smem[];
    float* vsb = smem;                 // 2-slot vertical-sum exchange
    float* dp  = smem + VS_FLOATS;     // per-warp deferred dot partials

    const int lane = threadIdx.x & 31;
    const int wid  = threadIdx.x >> 5;
    const int col  = blockIdx.x * COUT + wid - 1;     // wid 0 / NW-1 = halo
    const bool colok = ((unsigned)col < (unsigned)WW);
    const bool inner = (wid >= 1) && (wid <= COUT);
    const bool outok = colok && inner;
    const int r0 = blockIdx.y * ROWG;

    float* dprow = dp + wid * (BATCH * 33);
    // byte base for this thread's exchange lane; all other offsets are immediates
    char* vsc = reinterpret_cast<char*>(vsb) + wid * (CC * 4) + lane * 16;

    const float* gcol = in + (size_t)col * CC + lane * 4;
    const size_t rowstep = (size_t)WW * CC;
    auto ld = [&](int h) -> ulonglong2 {
        ulonglong2 v; v.x = 0ull; v.y = 0ull;
        if (colok && (unsigned)h < (unsigned)HH)
            v = *reinterpret_cast<const ulonglong2*>(gcol + (size_t)h * rowstep);
        return v;
    };
    auto scalev = [&](ulonglong2 v, float inv) -> ulonglong2 {
        const uint64_t ip = pack2(inv, inv);
        ulonglong2 r; r.x = f2mul(v.x, ip); r.y = f2mul(v.y, ip); return r;
    };

    // rolling normalized window + raw stages
    ulonglong2 xnP, xnA, xnB, stg0, stg1;
    {
        ulonglong2 ra = ld(r0 - 1), rb = ld(r0);
        float2 ss = redux2(dot4p(ra), dot4p(rb), lane);
        xnA = scalev(ra, (ss.x >= 1e-16f) ? rsqrtf(ss.x) : 1e8f);
        xnB = scalev(rb, (ss.y >= 1e-16f) ? rsqrtf(ss.y) : 1e8f);
        xnP = xnA;
    }
    stg0 = ld(r0 + 1);  stg1 = ld(r0 + 2);

    // produce rows (2k, 2k+1) into slot P; rotates xnP/xnA/xnB and stages.
    auto produce = [&](int k, int P) {
        const int h = r0 + 2 * k;
        float2 ss = redux2(dot4p(stg0), dot4p(stg1), lane);
        const ulonglong2 xnC = scalev(stg0, (ss.x >= 1e-16f) ? rsqrtf(ss.x) : 1e8f);
        const ulonglong2 xnD = scalev(stg1, (ss.y >= 1e-16f) ? rsqrtf(ss.y) : 1e8f);
        stg0 = ld(h + 3);
        stg1 = ld(h + 4);
        ulonglong2 v0, v1;
        v0.x = f2add(f2add(xnA.x, xnB.x), xnC.x);
        v0.y = f2add(f2add(xnA.y, xnB.y), xnC.y);
        v1.x = f2add(f2add(xnB.x, xnC.x), xnD.x);
        v1.y = f2add(f2add(xnB.y, xnC.y), xnD.y);
        *reinterpret_cast<ulonglong2*>(vsc + P * SLOTB)       = v0;
        *reinterpret_cast<ulonglong2*>(vsc + P * SLOTB + RPB) = v1;
        xnP = xnB;  xnA = xnC;  xnB = xnD;
    };

    // consume rows (i, i+1) = (2k-2, 2k-1) from slot NOTP; centers cen0, cen1.
    auto consume = [&](int i, int NOTP, ulonglong2 cen0, ulonglong2 cen1) {
        if (inner) {
            const char* c0 = vsc + NOTP * SLOTB;
            const ulonglong2 l0 = *reinterpret_cast<const ulonglong2*>(c0 - 512);
            const ulonglong2 o0 = *reinterpret_cast<const ulonglong2*>(c0);
            const ulonglong2 q0 = *reinterpret_cast<const ulonglong2*>(c0 + 512);
            const ulonglong2 l1 = *reinterpret_cast<const ulonglong2*>(c0 + RPB - 512);
            const ulonglong2 o1 = *reinterpret_cast<const ulonglong2*>(c0 + RPB);
            const ulonglong2 q1 = *reinterpret_cast<const ulonglong2*>(c0 + RPB + 512);

            uint64_t t0 = f2mul(cen0.x, f2add(f2add(l0.x, o0.x), q0.x));
            t0 = f2fma(cen0.y, f2add(f2add(l0.y, o0.y), q0.y), t0);
            uint64_t t1 = f2mul(cen1.x, f2add(f2add(l1.x, o1.x), q1.x));
            t1 = f2fma(cen1.y, f2add(f2add(l1.y, o1.y), q1.y), t1);

            dprow[(i & 31) * 33 + lane]       = hsum2(t0);
            dprow[((i + 1) & 31) * 33 + lane] = hsum2(t1);

            if ((i & 31) == 30) {
                __syncwarp();
                if (outok) {
                    float s = 0.f;
                    #pragma unroll
                    for (int j = 0; j < 32; j++) s += dprow[lane * 33 + j];
                    out[(size_t)(r0 + i - 30 + lane) * WW + col] = s - 1.0f;
                }
                __syncwarp();
            }
        }
    };

    // k=0: produce only
    produce(0, 0);
    __syncthreads();

    // k = 1..62 in parity pairs; slot offsets are immediates in each copy
    for (int k = 1; k < 63; k += 2) {
        {   // odd k: produce slot1, consume slot0
            const ulonglong2 c0 = xnP, c1 = xnA;
            produce(k, 1);
            consume(2 * k - 2, 0, c0, c1);
            __syncthreads();
        }
        {   // even k+1: produce slot0, consume slot1
            const ulonglong2 c0 = xnP, c1 = xnA;
            produce(k + 1, 0);
            consume(2 * k, 1, c0, c1);
            __syncthreads();
        }
    }
    // k=63 (odd): last produce + consume
    {
        const ulonglong2 c0 = xnP, c1 = xnA;
        produce(63, 1);
        consume(124, 0, c0, c1);
        __syncthreads();
    }
    // k=64: tail consume of rows 126,127 from slot1 (centers xnP, xnA)
    consume(126, 1, xnP, xnA);
}

extern "C" void kernel_launch(void* const* d_in, const int* in_sizes, int n_in,
                              void* d_out, int out_size)
{
    const float* in = (const float*)d_in[0];
    float* out = (float*)d_out;

    const size_t smem_bytes = SMEM_FLOATS * sizeof(float);   // ~98 KB
    cudaFuncSetAttribute(cos_sim_stream,
                         cudaFuncAttributeMaxDynamicSharedMemorySize,
                         (int)smem_bytes);

    dim3 grid((WW + COUT - 1) / COUT, HH / ROWG);   // 74 x 8
    cos_sim_stream<<<grid, TPB, smem_bytes>>>(in, out);
}

// round 16
// speedup vs baseline: 1.3559x; 1.2219x over previous
#include <cuda_runtime.h>
#include <cuda_fp16.h>
#include <math.h>
#include <cstdint>

#define HH 1024
#define WW 1024
#define CC 128
#define NW 16                 // warps per block = columns per block (incl. 2 halo)
#define TPB (NW * 32)
#define COUT (NW - 2)         // 14 output columns per block
#define ROWG 128              // rows per block
#define BATCH 32              // rows per deferred dot-reduce burst

// fp16 exchange: [parity(2)][rowpair(2)][warp(16)][lane(32)] x 8B = 16 KB
#define VSH_BYTES (2 * 2 * NW * 32 * 8)
#define VSH_FLOATS (VSH_BYTES / 4)         // 4096
#define DP_FLOATS (NW * BATCH * 33)        // 16896
#define SMEM_FLOATS (VSH_FLOATS + DP_FLOATS)

// ---- packed f32x2 primitives (sm_103a; PTX-only, ptxas won't auto-fuse) ----
__device__ __forceinline__ uint64_t f2mul(uint64_t a, uint64_t b) {
    uint64_t r; asm("mul.rn.f32x2 %0,%1,%2;" : "=l"(r) : "l"(a), "l"(b)); return r;
}
__device__ __forceinline__ uint64_t f2add(uint64_t a, uint64_t b) {
    uint64_t r; asm("add.rn.f32x2 %0,%1,%2;" : "=l"(r) : "l"(a), "l"(b)); return r;
}
__device__ __forceinline__ uint64_t f2fma(uint64_t a, uint64_t b, uint64_t c) {
    uint64_t r; asm("fma.rn.f32x2 %0,%1,%2,%3;" : "=l"(r) : "l"(a), "l"(b), "l"(c)); return r;
}
__device__ __forceinline__ uint64_t pack2(float x, float y) {
    uint64_t r; asm("mov.b64 %0,{%1,%2};" : "=l"(r) : "f"(x), "f"(y)); return r;
}
__device__ __forceinline__ float hsum2(uint64_t v) {
    float x, y; asm("mov.b64 {%0,%1},%2;" : "=f"(x), "=f"(y) : "l"(v)); return x + y;
}
__device__ __forceinline__ float dot4p(ulonglong2 v) {
    return hsum2(f2fma(v.y, v.y, f2mul(v.x, v.x)));
}

// f32x2 (as uint64) -> half2 (as uint32)
__device__ __forceinline__ uint32_t f2_to_h2(uint64_t v) {
    const float lo = __uint_as_float((uint32_t)v);
    const float hi = __uint_as_float((uint32_t)(v >> 32));
    uint32_t h;
    asm("cvt.rn.f16x2.f32 %0,%1,%2;" : "=r"(h) : "f"(hi), "f"(lo));  // hi->high, lo->low
    return h;
}
// half2 (as uint32) -> f32x2 (as uint64)
__device__ __forceinline__ uint64_t h2_to_f2(uint32_t h) {
    const __half2 hh = *reinterpret_cast<const __half2*>(&h);
    const float2 f = __half22float2(hh);
    return pack2(f.x, f.y);
}
__device__ __forceinline__ uint32_t h2add(uint32_t a, uint32_t b) {
    const __half2 r = __hadd2(*reinterpret_cast<const __half2*>(&a),
                              *reinterpret_cast<const __half2*>(&b));
    return *reinterpret_cast<const uint32_t*>(&r);
}

// reduce TWO independent values across the warp in one shared butterfly (6 SHFL)
__device__ __forceinline__ float2 redux2(float a, float b, int lane) {
    const unsigned full = 0xffffffffu;
    float z = (lane < 16) ? a : b;
    float w = (lane < 16) ? b : a;
    w = __shfl_xor_sync(full, w, 16);
    z += w;
    #pragma unroll
    for (int o = 8; o > 0; o >>= 1)
        z += __shfl_xor_sync(full, z, o);
    float t = __shfl_xor_sync(full, z, 16);
    float sa = (lane < 16) ? z : t;
    float sb = (lane < 16) ? t : z;
    return make_float2(sa, sb);
}

__global__ void __launch_bounds__(TPB, 2)
cos_sim_stream(const float* __restrict__ in, float* __restrict__ out)
{
    extern __shared__ float smem[];
    char*  vsc0 = reinterpret_cast<char*>(smem);   // fp16 exchange (16 KB)
    float* dp   = smem + VSH_FLOATS;               // per-warp deferred dot partials

    const int lane = threadIdx.x & 31;
    const int wid  = threadIdx.x >> 5;
    const int col  = blockIdx.x * COUT + wid - 1;     // wid 0 / NW-1 = halo
    const bool colok = ((unsigned)col < (unsigned)WW);
    const bool inner = (wid >= 1) && (wid <= COUT);
    const bool outok = colok && inner;
    const int r0 = blockIdx.y * ROWG;

    float* dprow = dp + wid * (BATCH * 33);
    // this thread's exchange address; slot/rowpair/neighbor offsets are immediates
    char* vsc = vsc0 + wid * 256 + lane * 8;

    const float* gcol = in + (size_t)col * CC + lane * 4;
    const size_t rowstep = (size_t)WW * CC;
    auto ld = [&](int h) -> ulonglong2 {
        ulonglong2 v; v.x = 0ull; v.y = 0ull;
        if (colok && (unsigned)h < (unsigned)HH)
            v = *reinterpret_cast<const ulonglong2*>(gcol + (size_t)h * rowstep);
        return v;
    };
    auto scalev = [&](ulonglong2 v, float inv) -> ulonglong2 {
        const uint64_t ip = pack2(inv, inv);
        ulonglong2 r; r.x = f2mul(v.x, ip); r.y = f2mul(v.y, ip); return r;
    };

    // ---- preamble: normalize rows r0-1, r0 (paired reduce); 4 rows staged ----
    ulonglong2 xnA, xnB;
    {
        ulonglong2 ra = ld(r0 - 1), rb = ld(r0);
        float2 ss = redux2(dot4p(ra), dot4p(rb), lane);
        xnA = scalev(ra, (ss.x >= 1e-16f) ? rsqrtf(ss.x) : 1e8f);
        xnB = scalev(rb, (ss.y >= 1e-16f) ? rsqrtf(ss.y) : 1e8f);
    }
    ulonglong2 stg[2][2];
    stg[0][0] = ld(r0 + 1);  stg[0][1] = ld(r0 + 2);
    stg[1][0] = ld(r0 + 3);  stg[1][1] = ld(r0 + 4);

    #pragma unroll 2
    for (int k = 0; k < ROWG / 2; k++) {
        const int i = 2 * k;
        const int h = r0 + i;
        const int p = k & 1;

        // normalize rows h+1, h+2 with ONE paired butterfly
        ulonglong2 s0 = stg[p][0], s1 = stg[p][1];
        float2 ss = redux2(dot4p(s0), dot4p(s1), lane);
        const ulonglong2 xnC = scalev(s0, (ss.x >= 1e-16f) ? rsqrtf(ss.x) : 1e8f);
        const ulonglong2 xnD = scalev(s1, (ss.y >= 1e-16f) ? rsqrtf(ss.y) : 1e8f);
        stg[p][0] = ld(h + 5);                 // refill, 4 rows ahead
        stg[p][1] = ld(h + 6);

        ulonglong2 v0, v1;                     // vertical 3-sums (f32x2 pairs)
        v0.x = f2add(f2add(xnA.x, xnB.x), xnC.x);
        v0.y = f2add(f2add(xnA.y, xnB.y), xnC.y);
        v1.x = f2add(f2add(xnB.x, xnC.x), xnD.x);
        v1.y = f2add(f2add(xnB.y, xnC.y), xnD.y);

        // publish vsums as half2 pairs (8B per lane, STS.64)
        char* st = vsc + p * 8192;
        *reinterpret_cast<uint2*>(st)        = make_uint2(f2_to_h2(v0.x), f2_to_h2(v0.y));
        *reinterpret_cast<uint2*>(st + 4096) = make_uint2(f2_to_h2(v1.x), f2_to_h2(v1.y));
        __syncthreads();                       // one barrier per 2 rows

        if (inner) {                           // warp-uniform
            const uint2 l0 = *reinterpret_cast<const uint2*>(st - 256);
            const uint2 q0 = *reinterpret_cast<const uint2*>(st + 256);
            const uint2 l1 = *reinterpret_cast<const uint2*>(st + 4096 - 256);
            const uint2 q1 = *reinterpret_cast<const uint2*>(st + 4096 + 256);

            // S = (l + q) in half2, widened, + own v (f32): then dot with center
            const uint64_t s0x = f2add(h2_to_f2(h2add(l0.x, q0.x)), v0.x);
            const uint64_t s0y = f2add(h2_to_f2(h2add(l0.y, q0.y)), v0.y);
            const uint64_t s1x = f2add(h2_to_f2(h2add(l1.x, q1.x)), v1.x);
            const uint64_t s1y = f2add(h2_to_f2(h2add(l1.y, q1.y)), v1.y);

            uint64_t t0 = f2mul(xnB.x, s0x);
            t0 = f2fma(xnB.y, s0y, t0);
            uint64_t t1 = f2mul(xnC.x, s1x);
            t1 = f2fma(xnC.y, s1y, t1);

            dprow[(i & 31) * 33 + lane]       = hsum2(t0);   // defer lane-reduce
            dprow[((i + 1) & 31) * 33 + lane] = hsum2(t1);

            if ((i & 31) == 30) {              // batch of 32 rows complete
                __syncwarp();
                if (outok) {
                    float s = 0.f;
                    #pragma unroll
                    for (int j = 0; j < 32; j++) s += dprow[lane * 33 + j];
                    out[(size_t)(h - 30 + lane) * WW + col] = s - 1.0f;
                }
                __syncwarp();
            }
        }
        xnA = xnC;  xnB = xnD;
    }
}

extern "C" void kernel_launch(void* const* d_in, const int* in_sizes, int n_in,
                              void* d_out, int out_size)
{
    const float* in = (const float*)d_in[0];
    float* out = (float*)d_out;

    const size_t smem_bytes = SMEM_FLOATS * sizeof(float);   // ~82 KB
    cudaFuncSetAttribute(cos_sim_stream,
                         cudaFuncAttributeMaxDynamicSharedMemorySize,
                         (int)smem_bytes);

    dim3 grid((WW + COUT - 1) / COUT, HH / ROWG);   // 74 x 8
    cos_sim_stream<<<grid, TPB, smem_bytes>>>(in, out);
}

// round 17
// speedup vs baseline: 1.3860x; 1.0222x over previous
#include <cuda_runtime.h>
#include <cuda_fp16.h>
#include <math.h>
#include <cstdint>

#define HH 1024
#define WW 1024
#define CC 128
#define NW 16                 // warps per block = columns per block (incl. 2 halo)
#define TPB (NW * 32)
#define COUT (NW - 2)         // 14 output columns per block
#define ROWG 128              // rows per block
#define BATCH 32              // rows per deferred dot-reduce burst

// fp16 exchange: [parity(2)][rowpair(2)][warp(16)][lane(32)] x 8B = 16 KB
#define VSH_BYTES (2 * 2 * NW * 32 * 8)
#define VSH_FLOATS (VSH_BYTES / 4)         // 4096
#define DP_FLOATS (NW * BATCH * 33)        // 16896
#define DSO_FLOATS (NW * 33)               // 528  output transpose tile
#define SMEM_FLOATS (VSH_FLOATS + DP_FLOATS + DSO_FLOATS)

// ---- packed f32x2 primitives (sm_103a; PTX-only, ptxas won't auto-fuse) ----
__device__ __forceinline__ uint64_t f2mul(uint64_t a, uint64_t b) {
    uint64_t r; asm("mul.rn.f32x2 %0,%1,%2;" : "=l"(r) : "l"(a), "l"(b)); return r;
}
__device__ __forceinline__ uint64_t f2add(uint64_t a, uint64_t b) {
    uint64_t r; asm("add.rn.f32x2 %0,%1,%2;" : "=l"(r) : "l"(a), "l"(b)); return r;
}
__device__ __forceinline__ uint64_t f2fma(uint64_t a, uint64_t b, uint64_t c) {
    uint64_t r; asm("fma.rn.f32x2 %0,%1,%2,%3;" : "=l"(r) : "l"(a), "l"(b), "l"(c)); return r;
}
__device__ __forceinline__ uint64_t pack2(float x, float y) {
    uint64_t r; asm("mov.b64 %0,{%1,%2};" : "=l"(r) : "f"(x), "f"(y)); return r;
}
__device__ __forceinline__ float hsum2(uint64_t v) {
    float x, y; asm("mov.b64 {%0,%1},%2;" : "=f"(x), "=f"(y) : "l"(v)); return x + y;
}
__device__ __forceinline__ float dot4p(ulonglong2 v) {
    return hsum2(f2fma(v.y, v.y, f2mul(v.x, v.x)));
}

// f32x2 (as uint64) -> half2 (as uint32)
__device__ __forceinline__ uint32_t f2_to_h2(uint64_t v) {
    const float lo = __uint_as_float((uint32_t)v);
    const float hi = __uint_as_float((uint32_t)(v >> 32));
    uint32_t h;
    asm("cvt.rn.f16x2.f32 %0,%1,%2;" : "=r"(h) : "f"(hi), "f"(lo));  // hi->high, lo->low
    return h;
}
// half2 (as uint32) -> f32x2 (as uint64)
__device__ __forceinline__ uint64_t h2_to_f2(uint32_t h) {
    const __half2 hh = *reinterpret_cast<const __half2*>(&h);
    const float2 f = __half22float2(hh);
    return pack2(f.x, f.y);
}
__device__ __forceinline__ uint32_t h2add(uint32_t a, uint32_t b) {
    const __half2 r = __hadd2(*reinterpret_cast<const __half2*>(&a),
                              *reinterpret_cast<const __half2*>(&b));
    return *reinterpret_cast<const uint32_t*>(&r);
}

// reduce TWO independent values across the warp in one shared butterfly (6 SHFL)
__device__ __forceinline__ float2 redux2(float a, float b, int lane) {
    const unsigned full = 0xffffffffu;
    float z = (lane < 16) ? a : b;
    float w = (lane < 16) ? b : a;
    w = __shfl_xor_sync(full, w, 16);
    z += w;
    #pragma unroll
    for (int o = 8; o > 0; o >>= 1)
        z += __shfl_xor_sync(full, z, o);
    float t = __shfl_xor_sync(full, z, 16);
    float sa = (lane < 16) ? z : t;
    float sb = (lane < 16) ? t : z;
    return make_float2(sa, sb);
}

__global__ void __launch_bounds__(TPB, 2)
cos_sim_stream(const float* __restrict__ in, float* __restrict__ out)
{
    extern __shared__ float smem[];
    char*  vsc0 = reinterpret_cast<char*>(smem);   // fp16 exchange (16 KB)
    float* dp   = smem + VSH_FLOATS;               // per-warp deferred dot partials
    float* dso  = dp + DP_FLOATS;                  // [col_warp][row] output tile

    const int lane = threadIdx.x & 31;
    const int wid  = threadIdx.x >> 5;
    const int col  = blockIdx.x * COUT + wid - 1;     // wid 0 / NW-1 = halo
    const bool colok = ((unsigned)col < (unsigned)WW);
    const bool inner = (wid >= 1) && (wid <= COUT);
    const int r0 = blockIdx.y * ROWG;
    const int ocol0 = blockIdx.x * COUT;              // first output column

    float* dprow = dp + wid * (BATCH * 33);
    // this thread's exchange address; slot/rowpair/neighbor offsets are immediates
    char* vsc = vsc0 + wid * 256 + lane * 8;

    const float* gcol = in + (size_t)col * CC + lane * 4;
    const size_t rowstep = (size_t)WW * CC;
    auto ld = [&](int h) -> ulonglong2 {
        ulonglong2 v; v.x = 0ull; v.y = 0ull;
        if (colok && (unsigned)h < (unsigned)HH)
            v = *reinterpret_cast<const ulonglong2*>(gcol + (size_t)h * rowstep);
        return v;
    };
    auto scalev = [&](ulonglong2 v, float inv) -> ulonglong2 {
        const uint64_t ip = pack2(inv, inv);
        ulonglong2 r; r.x = f2mul(v.x, ip); r.y = f2mul(v.y, ip); return r;
    };
    // cooperative, coalesced store of one 32-row x 14-col batch (base row hb)
    auto store_batch = [&](int hb) {
        const int t = threadIdx.x;
        if (t < BATCH * COUT) {
            const int row = t / COUT;
            const int c   = t - row * COUT;
            const int oc  = ocol0 + c;
            if (oc < WW)
                out[(size_t)(hb + row) * WW + oc] = dso[(c + 1) * 33 + row];
        }
    };

    // ---- preamble: normalize rows r0-1, r0 (paired reduce); 4 rows staged ----
    ulonglong2 xnA, xnB;
    {
        ulonglong2 ra = ld(r0 - 1), rb = ld(r0);
        float2 ss = redux2(dot4p(ra), dot4p(rb), lane);
        xnA = scalev(ra, (ss.x >= 1e-16f) ? rsqrtf(ss.x) : 1e8f);
        xnB = scalev(rb, (ss.y >= 1e-16f) ? rsqrtf(ss.y) : 1e8f);
    }
    ulonglong2 stg[2][2];
    stg[0][0] = ld(r0 + 1);  stg[0][1] = ld(r0 + 2);
    stg[1][0] = ld(r0 + 3);  stg[1][1] = ld(r0 + 4);

    #pragma unroll 2
    for (int k = 0; k < ROWG / 2; k++) {
        const int i = 2 * k;
        const int h = r0 + i;
        const int p = k & 1;

        // normalize rows h+1, h+2 with ONE paired butterfly
        ulonglong2 s0 = stg[p][0], s1 = stg[p][1];
        float2 ss = redux2(dot4p(s0), dot4p(s1), lane);
        const ulonglong2 xnC = scalev(s0, (ss.x >= 1e-16f) ? rsqrtf(ss.x) : 1e8f);
        const ulonglong2 xnD = scalev(s1, (ss.y >= 1e-16f) ? rsqrtf(ss.y) : 1e8f);
        stg[p][0] = ld(h + 5);                 // refill, 4 rows ahead
        stg[p][1] = ld(h + 6);

        ulonglong2 v0, v1;                     // vertical 3-sums (f32x2 pairs)
        v0.x = f2add(f2add(xnA.x, xnB.x), xnC.x);
        v0.y = f2add(f2add(xnA.y, xnB.y), xnC.y);
        v1.x = f2add(f2add(xnB.x, xnC.x), xnD.x);
        v1.y = f2add(f2add(xnB.y, xnC.y), xnD.y);

        // publish vsums as half2 pairs (8B per lane, STS.64)
        char* st = vsc + p * 8192;
        *reinterpret_cast<uint2*>(st)        = make_uint2(f2_to_h2(v0.x), f2_to_h2(v0.y));
        *reinterpret_cast<uint2*>(st + 4096) = make_uint2(f2_to_h2(v1.x), f2_to_h2(v1.y));
        __syncthreads();                       // one barrier per 2 rows

        // coalesced store of the PREVIOUS batch (dso complete + barrier passed)
        if ((i & 31) == 0 && i > 0)
            store_batch(r0 + i - 32);

        if (inner) {                           // warp-uniform
            const uint2 l0 = *reinterpret_cast<const uint2*>(st - 256);
            const uint2 q0 = *reinterpret_cast<const uint2*>(st + 256);
            const uint2 l1 = *reinterpret_cast<const uint2*>(st + 4096 - 256);
            const uint2 q1 = *reinterpret_cast<const uint2*>(st + 4096 + 256);

            // S = (l + q) in half2, widened, + own v (f32): then dot with center
            const uint64_t s0x = f2add(h2_to_f2(h2add(l0.x, q0.x)), v0.x);
            const uint64_t s0y = f2add(h2_to_f2(h2add(l0.y, q0.y)), v0.y);
            const uint64_t s1x = f2add(h2_to_f2(h2add(l1.x, q1.x)), v1.x);
            const uint64_t s1y = f2add(h2_to_f2(h2add(l1.y, q1.y)), v1.y);

            uint64_t t0 = f2mul(xnB.x, s0x);
            t0 = f2fma(xnB.y, s0y, t0);
            uint64_t t1 = f2mul(xnC.x, s1x);
            t1 = f2fma(xnC.y, s1y, t1);

            dprow[(i & 31) * 33 + lane]       = hsum2(t0);   // defer lane-reduce
            dprow[((i + 1) & 31) * 33 + lane] = hsum2(t1);

            if ((i & 31) == 30) {              // batch of 32 rows complete
                __syncwarp();
                float s = 0.f;
                #pragma unroll
                for (int j = 0; j < 32; j++) s += dprow[lane * 33 + j];
                dso[wid * 33 + lane] = s - 1.0f;   // lane = row within batch
                __syncwarp();
            }
        }
        xnA = xnC;  xnB = xnD;
    }

    // trailing batch (rows r0+96 .. r0+127)
    __syncthreads();
    store_batch(r0 + ROWG - 32);
}

extern "C" void kernel_launch(void* const* d_in, const int* in_sizes, int n_in,
                              void* d_out, int out_size)
{
    const float* in = (const float*)d_in[0];
    float* out = (float*)d_out;

    const size_t smem_bytes = SMEM_FLOATS * sizeof(float);   // ~84 KB
    cudaFuncSetAttribute(cos_sim_stream,
                         cudaFuncAttributeMaxDynamicSharedMemorySize,
                         (int)smem_bytes);

    dim3 grid((WW + COUT - 1) / COUT, HH / ROWG);   // 74 x 8
    cos_sim_stream<<<grid, TPB, smem_bytes>>>(in, out);
}